// round 16
// baseline (speedup 1.0000x reference)
#include <cuda_runtime.h>
#include <cuda_bf16.h>
#include <math.h>
#include <stdint.h>

#define T_TOK 4096
#define DIM   1024
#define NEXP  8
#define WEXP  1024
#define EW    8192
#define PMAX  9216
#define NRT   72

#define BM 128
#define BN 128
#define BK 16
#define PADA 12      // uint32 words per A smem row (8 data + 4 pad) = 48B
#define BROW 136     // uint32 words per B smem row ([kp][n] layout, 128 + 8 pad)

// ---------------- MMA + pack helpers ----------------
#define MMA16816(c, a, b0, b1) \
    asm volatile("mma.sync.aligned.m16n8k16.row.col.f32.bf16.bf16.f32 " \
        "{%0,%1,%2,%3}, {%4,%5,%6,%7}, {%8,%9}, {%0,%1,%2,%3};" \
        : "+f"((c)[0]), "+f"((c)[1]), "+f"((c)[2]), "+f"((c)[3]) \
        : "r"((a)[0]), "r"((a)[1]), "r"((a)[2]), "r"((a)[3]), "r"(b0), "r"(b1))

__device__ __forceinline__ uint32_t pack2(__nv_bfloat16 a, __nv_bfloat16 b) {
    return ((uint32_t)__bfloat16_as_ushort(b) << 16) | __bfloat16_as_ushort(a);
}
// fp32 pair -> bf16 hi pair + bf16 lo (residual) pair   (low half = v.x)
__device__ __forceinline__ void cvt_hilo(float2 v, uint32_t& hi, uint32_t& lo) {
    __nv_bfloat16 h0 = __float2bfloat16_rn(v.x);
    __nv_bfloat16 h1 = __float2bfloat16_rn(v.y);
    hi = pack2(h0, h1);
    __nv_bfloat16 l0 = __float2bfloat16_rn(v.x - __bfloat162float(h0));
    __nv_bfloat16 l1 = __float2bfloat16_rn(v.y - __bfloat162float(h1));
    lo = pack2(l0, l1);
}

// ---------------- device scratch (total ~88 MB, the proven-passing level) ---
__device__ uint32_t g_xp_h[(size_t)T_TOK * (DIM / 2)];   // x packed bf16x2 hi (k-pairs)
__device__ uint32_t g_xp_l[(size_t)T_TOK * (DIM / 2)];
__device__ uint32_t g_ap_h[(size_t)PMAX * (WEXP / 2)];   // activations hi
__device__ uint32_t g_ap_l[(size_t)PMAX * (WEXP / 2)];
// Shared weight-pack buffer: holds w1 (prep->gemm_up), then w2 (gemm_down).
// Both need exactly (DIM/2)*EW == (EW/2)*DIM = 4.19M words per array.
__device__ uint32_t g_wp_h[(size_t)(DIM / 2) * EW];
__device__ uint32_t g_wp_l[(size_t)(DIM / 2) * EW];
__device__ int   g_pairid[PMAX];
__device__ float g_pairwt[PMAX];
__device__ int   g_sel[T_TOK * 2];
__device__ float g_wt[T_TOK * 2];
__device__ int   g_cnt[NEXP];
__device__ int   g_cursor[NEXP];
__device__ int   g_tile_e[NRT];

// ---------------- small kernels (verbatim, proven) ----------------
__global__ void k_reset() {
    if (threadIdx.x < NEXP) g_cnt[threadIdx.x] = 0;
}

__global__ __launch_bounds__(256) void k_router(const float* __restrict__ x,
                                                const float* __restrict__ rw) {
    __shared__ float s_rw[NEXP * DIM];
    for (int i = threadIdx.x; i < NEXP * DIM; i += blockDim.x) s_rw[i] = rw[i];
    __syncthreads();
    const int warp = threadIdx.x >> 5, lane = threadIdx.x & 31;
    const int t = blockIdx.x * 8 + warp;
    if (t >= T_TOK) return;
    const float* xr = x + (size_t)t * DIM;
    float acc[NEXP];
#pragma unroll
    for (int e = 0; e < NEXP; e++) acc[e] = 0.f;
    for (int d = lane; d < DIM; d += 32) {
        float xv = xr[d];
#pragma unroll
        for (int e = 0; e < NEXP; e++) acc[e] += xv * s_rw[e * DIM + d];
    }
#pragma unroll
    for (int e = 0; e < NEXP; e++)
#pragma unroll
        for (int off = 16; off; off >>= 1)
            acc[e] += __shfl_xor_sync(0xffffffffu, acc[e], off);
    if (lane == 0) {
        float best = -1e30f, sec = -1e30f; int bi = 0, si = 0;
#pragma unroll
        for (int e = 0; e < NEXP; e++) {
            float p = 1.f / (1.f + expf(-acc[e]));
            if (p > best) { sec = best; si = bi; best = p; bi = e; }
            else if (p > sec) { sec = p; si = e; }
        }
        float s = best + sec + 1e-20f;
        g_sel[t * 2 + 0] = bi; g_sel[t * 2 + 1] = si;
        g_wt[t * 2 + 0] = best / s; g_wt[t * 2 + 1] = sec / s;
        atomicAdd(&g_cnt[bi], 1); atomicAdd(&g_cnt[si], 1);
    }
}

__global__ void k_setup() {
    if (threadIdx.x == 0) {
        int offs[NEXP + 1]; offs[0] = 0;
        for (int e = 0; e < NEXP; e++) {
            g_cursor[e] = offs[e];
            offs[e + 1] = offs[e] + ((g_cnt[e] + 127) & ~127);
        }
        for (int r = 0; r < NRT; r++) {
            int rb = r * 128, ee = -1;
            for (int e = 0; e < NEXP; e++)
                if (rb >= offs[e] && rb < offs[e + 1]) ee = e;
            g_tile_e[r] = ee;
        }
    }
    for (int i = threadIdx.x; i < PMAX; i += blockDim.x) {
        g_pairid[i] = -1; g_pairwt[i] = 0.f;
    }
}

__global__ void k_scatter() {
    int t = blockIdx.x * blockDim.x + threadIdx.x;
    if (t >= T_TOK) return;
#pragma unroll
    for (int k = 0; k < 2; k++) {
        int e = g_sel[t * 2 + k];
        int pos = atomicAdd(&g_cursor[e], 1);
        g_pairid[pos] = t * 2 + k;
        g_pairwt[pos] = g_wt[t * 2 + k];
    }
}

// ---------------- prep: x -> packed bf16x2 hi/lo (k-pairs within a row) ----
__global__ __launch_bounds__(256) void k_prep_x(const float* __restrict__ x) {
    int g = blockIdx.x * blockDim.x + threadIdx.x;   // float4 index
    float4 v = *(const float4*)(x + (size_t)g * 4);
    uint32_t h01, l01, h23, l23;
    cvt_hilo(make_float2(v.x, v.y), h01, l01);
    cvt_hilo(make_float2(v.z, v.w), h23, l23);
    *(uint2*)(g_xp_h + (size_t)g * 2) = make_uint2(h01, h23);
    *(uint2*)(g_xp_l + (size_t)g * 2) = make_uint2(l01, l23);
}

// ---- prep: weights -> k-pair-packed bf16x2 hi/lo, layout == B smem tiles ---
// src is [K][N] row-major; out word[pk][n] = pack(src[2pk][n], src[2pk+1][n]).
__global__ __launch_bounds__(256) void k_prep_w(const float* __restrict__ src,
                                                int N) {
    const int pk = blockIdx.y;
    const int nq = blockIdx.x * blockDim.x + threadIdx.x;   // n/4
    if (nq * 4 >= N) return;
    const float* r0 = src + (size_t)(2 * pk) * N + nq * 4;
    const float4 a = *(const float4*)r0;
    const float4 b = *(const float4*)(r0 + N);
    uint32_t h[4], l[4];
    cvt_hilo(make_float2(a.x, b.x), h[0], l[0]);
    cvt_hilo(make_float2(a.y, b.y), h[1], l[1]);
    cvt_hilo(make_float2(a.z, b.z), h[2], l[2]);
    cvt_hilo(make_float2(a.w, b.w), h[3], l[3]);
    const size_t o = (size_t)pk * N + nq * 4;
    *(uint4*)(g_wp_h + o) = make_uint4(h[0], h[1], h[2], h[3]);
    *(uint4*)(g_wp_l + o) = make_uint4(l[0], l[1], l[2], l[3]);
}

__global__ void k_zero_out(float* __restrict__ out) {
    const int i = blockIdx.x * blockDim.x + threadIdx.x;
    ((float4*)out)[i] = make_float4(0.f, 0.f, 0.f, 0.f);
}

// ---------------- up-proj: HMMA bf16x3, fully pre-packed operands ----------
__global__ __launch_bounds__(256) void k_gemm_up(void) {
    const int r = blockIdx.y;
    const int e = g_tile_e[r];
    if (e < 0) return;
    const int cb = blockIdx.x;
    const int base = r * BM;

    __shared__ uint32_t Ah[2][BM][PADA], Al[2][BM][PADA];
    __shared__ uint32_t Bh[2][8][BROW], Bl[2][8][BROW];

    const int tid = threadIdx.x, lane = tid & 31, wid = tid >> 5;
    const int wm = wid & 3, wn = wid >> 2;
    const int gid = lane >> 2, tig = lane & 3;

    // A loader: 1 thread per (array, row); 2x uint4 = the row's 16-k chunk
    const int aarr = tid >> 7;               // 0 = hi, 1 = lo
    const int arow = tid & 127;
    const int pid = g_pairid[base + arow];
    const int rowsrc = (pid >= 0) ? (pid >> 1) : 0;
    const uint32_t* asrc = (aarr ? g_xp_l : g_xp_h) + (size_t)rowsrc * (DIM / 2);

    // B loader: kp row, 4 consecutive n words; hi + lo at same index
    const int kp = tid >> 5;                 // 0..7
    const int n0 = (tid & 31) * 4;           // 0..124
    const size_t bcol = (size_t)(e * WEXP + cb * BN + n0);
    const uint32_t* bh_src = g_wp_h + bcol;
    const uint32_t* bl_src = g_wp_l + bcol;

    {   // prologue -> stage 0
        uint4 a0 = *(const uint4*)(asrc);
        uint4 a1 = *(const uint4*)(asrc + 4);
        uint32_t (*Ad)[PADA] = aarr ? Al[0] : Ah[0];
        *(uint4*)&Ad[arow][0] = a0;
        *(uint4*)&Ad[arow][4] = a1;
        *(uint4*)&Bh[0][kp][n0] = *(const uint4*)(bh_src + (size_t)kp * EW);
        *(uint4*)&Bl[0][kp][n0] = *(const uint4*)(bl_src + (size_t)kp * EW);
    }
    __syncthreads();

    float acc[2][8][4];
#pragma unroll
    for (int mi = 0; mi < 2; mi++)
#pragma unroll
        for (int ni = 0; ni < 8; ni++)
#pragma unroll
            for (int c = 0; c < 4; c++) acc[mi][ni][c] = 0.f;

    const int NKT = DIM / BK;
    for (int kt = 0; kt < NKT; kt++) {
        const int cur = kt & 1;
        uint4 na0, na1, nbh4, nbl4;
        if (kt + 1 < NKT) {
            na0 = *(const uint4*)(asrc + (kt + 1) * 8);
            na1 = *(const uint4*)(asrc + (kt + 1) * 8 + 4);
            const size_t kq = (size_t)((kt + 1) * 8 + kp) * EW;
            nbh4 = *(const uint4*)(bh_src + kq);
            nbl4 = *(const uint4*)(bl_src + kq);
        }

        // A fragments: a0=(row,kp=tig) a1=(row+8,tig) a2=(row,tig+4) a3=(row+8,tig+4)
        uint32_t ah[2][4], al[2][4];
#pragma unroll
        for (int mi = 0; mi < 2; mi++) {
            const int row = wm * 32 + mi * 16 + gid;
            ah[mi][0] = Ah[cur][row][tig];     al[mi][0] = Al[cur][row][tig];
            ah[mi][1] = Ah[cur][row + 8][tig]; al[mi][1] = Al[cur][row + 8][tig];
            ah[mi][2] = Ah[cur][row][tig + 4]; al[mi][2] = Al[cur][row][tig + 4];
            ah[mi][3] = Ah[cur][row + 8][tig + 4];
            al[mi][3] = Al[cur][row + 8][tig + 4];
        }
        // B fragments: b0=(kp=tig, n) b1=(kp=tig+4, n)
#pragma unroll
        for (int t8 = 0; t8 < 8; t8++) {
            const int n = wn * 64 + t8 * 8 + gid;
            uint32_t bh0 = Bh[cur][tig][n],     bh1 = Bh[cur][tig + 4][n];
            uint32_t bl0 = Bl[cur][tig][n],     bl1 = Bl[cur][tig + 4][n];
#pragma unroll
            for (int mi = 0; mi < 2; mi++) {
                float* c = acc[mi][t8];
                MMA16816(c, ah[mi], bh0, bh1);
                MMA16816(c, al[mi], bh0, bh1);
                MMA16816(c, ah[mi], bl0, bl1);
            }
        }

        if (kt + 1 < NKT) {
            const int nxt = cur ^ 1;
            uint32_t (*Ad)[PADA] = aarr ? Al[nxt] : Ah[nxt];
            *(uint4*)&Ad[arow][0] = na0;
            *(uint4*)&Ad[arow][4] = na1;
            *(uint4*)&Bh[nxt][kp][n0] = nbh4;
            *(uint4*)&Bl[nxt][kp][n0] = nbl4;
        }
        __syncthreads();
    }

    // epilogue: relu^2 -> packed hi/lo activation pairs
#pragma unroll
    for (int mi = 0; mi < 2; mi++) {
        const int row0 = base + wm * 32 + mi * 16 + gid;
        const int row1 = row0 + 8;
#pragma unroll
        for (int t8 = 0; t8 < 8; t8++) {
            const int col = cb * BN + wn * 64 + t8 * 8 + tig * 2;   // even
            float v0 = acc[mi][t8][0], v1 = acc[mi][t8][1];
            float v2 = acc[mi][t8][2], v3 = acc[mi][t8][3];
            v0 = fmaxf(v0, 0.f); v0 *= v0;
            v1 = fmaxf(v1, 0.f); v1 *= v1;
            v2 = fmaxf(v2, 0.f); v2 *= v2;
            v3 = fmaxf(v3, 0.f); v3 *= v3;
            uint32_t h01, l01, h23, l23;
            cvt_hilo(make_float2(v0, v1), h01, l01);
            cvt_hilo(make_float2(v2, v3), h23, l23);
            const size_t p0 = (size_t)row0 * (WEXP / 2) + (col >> 1);
            const size_t p1 = (size_t)row1 * (WEXP / 2) + (col >> 1);
            g_ap_h[p0] = h01; g_ap_l[p0] = l01;
            g_ap_h[p1] = h23; g_ap_l[p1] = l23;
        }
    }
}

// ---------------- down-proj: same engine, atomic scatter into out ----------
// Each out element receives exactly 2 atomic contributions (the token's two
// slots); 2-term float addition is commutative, so the result is bitwise
// deterministic regardless of arrival order.
__global__ __launch_bounds__(256) void k_gemm_down(float* __restrict__ out) {
    const int r = blockIdx.y;
    const int e = g_tile_e[r];
    if (e < 0) return;
    const int cb = blockIdx.x;
    const int base = r * BM;

    __shared__ uint32_t Ah[2][BM][PADA], Al[2][BM][PADA];
    __shared__ uint32_t Bh[2][8][BROW], Bl[2][8][BROW];

    const int tid = threadIdx.x, lane = tid & 31, wid = tid >> 5;
    const int wm = wid & 3, wn = wid >> 2;
    const int gid = lane >> 2, tig = lane & 3;

    const int aarr = tid >> 7;
    const int arow = tid & 127;
    const uint32_t* asrc = (aarr ? g_ap_l : g_ap_h) + (size_t)(base + arow) * (WEXP / 2);

    const int kp = tid >> 5;
    const int n0 = (tid & 31) * 4;
    const size_t bbase_off = (size_t)(e * (WEXP / 2)) * DIM + (size_t)(cb * BN + n0);
    const uint32_t* bh_src = g_wp_h + bbase_off;
    const uint32_t* bl_src = g_wp_l + bbase_off;

    {
        uint4 a0 = *(const uint4*)(asrc);
        uint4 a1 = *(const uint4*)(asrc + 4);
        uint32_t (*Ad)[PADA] = aarr ? Al[0] : Ah[0];
        *(uint4*)&Ad[arow][0] = a0;
        *(uint4*)&Ad[arow][4] = a1;
        *(uint4*)&Bh[0][kp][n0] = *(const uint4*)(bh_src + (size_t)kp * DIM);
        *(uint4*)&Bl[0][kp][n0] = *(const uint4*)(bl_src + (size_t)kp * DIM);
    }
    __syncthreads();

    float acc[2][8][4];
#pragma unroll
    for (int mi = 0; mi < 2; mi++)
#pragma unroll
        for (int ni = 0; ni < 8; ni++)
#pragma unroll
            for (int c = 0; c < 4; c++) acc[mi][ni][c] = 0.f;

    const int NKT = WEXP / BK;
    for (int kt = 0; kt < NKT; kt++) {
        const int cur = kt & 1;
        uint4 na0, na1, nbh4, nbl4;
        if (kt + 1 < NKT) {
            na0 = *(const uint4*)(asrc + (kt + 1) * 8);
            na1 = *(const uint4*)(asrc + (kt + 1) * 8 + 4);
            const size_t kq = (size_t)((kt + 1) * 8 + kp) * DIM;
            nbh4 = *(const uint4*)(bh_src + kq);
            nbl4 = *(const uint4*)(bl_src + kq);
        }

        uint32_t ah[2][4], al[2][4];
#pragma unroll
        for (int mi = 0; mi < 2; mi++) {
            const int row = wm * 32 + mi * 16 + gid;
            ah[mi][0] = Ah[cur][row][tig];     al[mi][0] = Al[cur][row][tig];
            ah[mi][1] = Ah[cur][row + 8][tig]; al[mi][1] = Al[cur][row + 8][tig];
            ah[mi][2] = Ah[cur][row][tig + 4]; al[mi][2] = Al[cur][row][tig + 4];
            ah[mi][3] = Ah[cur][row + 8][tig + 4];
            al[mi][3] = Al[cur][row + 8][tig + 4];
        }
#pragma unroll
        for (int t8 = 0; t8 < 8; t8++) {
            const int n = wn * 64 + t8 * 8 + gid;
            uint32_t bh0 = Bh[cur][tig][n],     bh1 = Bh[cur][tig + 4][n];
            uint32_t bl0 = Bl[cur][tig][n],     bl1 = Bl[cur][tig + 4][n];
#pragma unroll
            for (int mi = 0; mi < 2; mi++) {
                float* c = acc[mi][t8];
                MMA16816(c, ah[mi], bh0, bh1);
                MMA16816(c, al[mi], bh0, bh1);
                MMA16816(c, ah[mi], bl0, bl1);
            }
        }

        if (kt + 1 < NKT) {
            const int nxt = cur ^ 1;
            uint32_t (*Ad)[PADA] = aarr ? Al[nxt] : Ah[nxt];
            *(uint4*)&Ad[arow][0] = na0;
            *(uint4*)&Ad[arow][4] = na1;
            *(uint4*)&Bh[nxt][kp][n0] = nbh4;
            *(uint4*)&Bl[nxt][kp][n0] = nbl4;
        }
        __syncthreads();
    }

    // epilogue: router-weight scale + atomic scatter (2 adds per element total)
#pragma unroll
    for (int mi = 0; mi < 2; mi++) {
        const int row0 = base + wm * 32 + mi * 16 + gid;
        const int row1 = row0 + 8;
        const int pid0 = g_pairid[row0], pid1 = g_pairid[row1];
        const float wt0 = g_pairwt[row0], wt1 = g_pairwt[row1];
        float* d0 = (pid0 >= 0) ? out + (size_t)(pid0 >> 1) * DIM : nullptr;
        float* d1 = (pid1 >= 0) ? out + (size_t)(pid1 >> 1) * DIM : nullptr;
#pragma unroll
        for (int t8 = 0; t8 < 8; t8++) {
            const int col = cb * BN + wn * 64 + t8 * 8 + tig * 2;
            if (d0) {
                atomicAdd(d0 + col,     wt0 * acc[mi][t8][0]);
                atomicAdd(d0 + col + 1, wt0 * acc[mi][t8][1]);
            }
            if (d1) {
                atomicAdd(d1 + col,     wt1 * acc[mi][t8][2]);
                atomicAdd(d1 + col + 1, wt1 * acc[mi][t8][3]);
            }
        }
    }
}

extern "C" void kernel_launch(void* const* d_in, const int* in_sizes, int n_in,
                              void* d_out, int out_size) {
    const float* x  = (const float*)d_in[0];   // [4096, 1024]
    const float* rw = (const float*)d_in[1];   // [8, 1024]
    const float* w1 = (const float*)d_in[2];   // [1024, 8192]
    const float* w2 = (const float*)d_in[3];   // [8192, 1024]
    float* out = (float*)d_out;

    k_reset<<<1, 32>>>();
    k_router<<<T_TOK / 8, 256>>>(x, rw);
    k_setup<<<1, 256>>>();
    k_scatter<<<T_TOK / 256, 256>>>();
    k_prep_x<<<(T_TOK * DIM / 4) / 256, 256>>>(x);
    k_prep_w<<<dim3(EW / 4 / 256, DIM / 2), 256>>>(w1, EW);      // w1 -> g_wp
    k_gemm_up<<<dim3(WEXP / BN, NRT), 256>>>();
    k_prep_w<<<dim3(1, EW / 2), 256>>>(w2, DIM);                 // w2 -> g_wp (reuse)
    k_zero_out<<<(T_TOK * DIM / 4) / 256, 256>>>(out);
    k_gemm_down<<<dim3(DIM / BN, NRT), 256>>>(out);
}

// round 17
// speedup vs baseline: 1.5563x; 1.5563x over previous
#include <cuda_runtime.h>
#include <cuda_bf16.h>
#include <math.h>
#include <stdint.h>

#define T_TOK 4096
#define DIM   1024
#define NEXP  8
#define WEXP  1024
#define EW    8192
#define PMAX  9216
#define NRT   72

#define BM 128
#define BN 128
#define BK 16
#define PADA 12      // uint32 words per A smem row (8 data + 4 pad) = 48B
#define BROW 136     // uint32 words per B smem row ([kp][n] layout, 128 + 8 pad)

// ---------------- MMA + pack helpers ----------------
#define MMA16816(c, a, b0, b1) \
    asm volatile("mma.sync.aligned.m16n8k16.row.col.f32.bf16.bf16.f32 " \
        "{%0,%1,%2,%3}, {%4,%5,%6,%7}, {%8,%9}, {%0,%1,%2,%3};" \
        : "+f"((c)[0]), "+f"((c)[1]), "+f"((c)[2]), "+f"((c)[3]) \
        : "r"((a)[0]), "r"((a)[1]), "r"((a)[2]), "r"((a)[3]), "r"(b0), "r"(b1))

__device__ __forceinline__ uint32_t pack2(__nv_bfloat16 a, __nv_bfloat16 b) {
    return ((uint32_t)__bfloat16_as_ushort(b) << 16) | __bfloat16_as_ushort(a);
}
// fp32 pair -> bf16 hi pair + bf16 lo (residual) pair   (low half = v.x)
__device__ __forceinline__ void cvt_hilo(float2 v, uint32_t& hi, uint32_t& lo) {
    __nv_bfloat16 h0 = __float2bfloat16_rn(v.x);
    __nv_bfloat16 h1 = __float2bfloat16_rn(v.y);
    hi = pack2(h0, h1);
    __nv_bfloat16 l0 = __float2bfloat16_rn(v.x - __bfloat162float(h0));
    __nv_bfloat16 l1 = __float2bfloat16_rn(v.y - __bfloat162float(h1));
    lo = pack2(l0, l1);
}

// ---------------- device scratch (~88 MB total, the proven-passing level) ---
__device__ uint32_t g_xp_h[(size_t)T_TOK * (DIM / 2)];   // x packed bf16x2 hi (k-pairs)
__device__ uint32_t g_xp_l[(size_t)T_TOK * (DIM / 2)];
__device__ uint32_t g_ap_h[(size_t)PMAX * (WEXP / 2)];   // activations hi
__device__ uint32_t g_ap_l[(size_t)PMAX * (WEXP / 2)];
__device__ float g_part[(size_t)2 * T_TOK * DIM];
__device__ int   g_pairid[PMAX];
__device__ float g_pairwt[PMAX];
__device__ int   g_sel[T_TOK * 2];
__device__ float g_wt[T_TOK * 2];
__device__ int   g_cnt[NEXP];
__device__ int   g_cursor[NEXP];
__device__ int   g_tile_e[NRT];

// ---------------- small kernels (verbatim, proven) ----------------
__global__ void k_reset() {
    if (threadIdx.x < NEXP) g_cnt[threadIdx.x] = 0;
}

__global__ __launch_bounds__(256) void k_router(const float* __restrict__ x,
                                                const float* __restrict__ rw) {
    __shared__ float s_rw[NEXP * DIM];
    for (int i = threadIdx.x; i < NEXP * DIM; i += blockDim.x) s_rw[i] = rw[i];
    __syncthreads();
    const int warp = threadIdx.x >> 5, lane = threadIdx.x & 31;
    const int t = blockIdx.x * 8 + warp;
    if (t >= T_TOK) return;
    const float* xr = x + (size_t)t * DIM;
    float acc[NEXP];
#pragma unroll
    for (int e = 0; e < NEXP; e++) acc[e] = 0.f;
    for (int d = lane; d < DIM; d += 32) {
        float xv = xr[d];
#pragma unroll
        for (int e = 0; e < NEXP; e++) acc[e] += xv * s_rw[e * DIM + d];
    }
#pragma unroll
    for (int e = 0; e < NEXP; e++)
#pragma unroll
        for (int off = 16; off; off >>= 1)
            acc[e] += __shfl_xor_sync(0xffffffffu, acc[e], off);
    if (lane == 0) {
        float best = -1e30f, sec = -1e30f; int bi = 0, si = 0;
#pragma unroll
        for (int e = 0; e < NEXP; e++) {
            float p = 1.f / (1.f + expf(-acc[e]));
            if (p > best) { sec = best; si = bi; best = p; bi = e; }
            else if (p > sec) { sec = p; si = e; }
        }
        float s = best + sec + 1e-20f;
        g_sel[t * 2 + 0] = bi; g_sel[t * 2 + 1] = si;
        g_wt[t * 2 + 0] = best / s; g_wt[t * 2 + 1] = sec / s;
        atomicAdd(&g_cnt[bi], 1); atomicAdd(&g_cnt[si], 1);
    }
}

__global__ void k_setup() {
    if (threadIdx.x == 0) {
        int offs[NEXP + 1]; offs[0] = 0;
        for (int e = 0; e < NEXP; e++) {
            g_cursor[e] = offs[e];
            offs[e + 1] = offs[e] + ((g_cnt[e] + 127) & ~127);
        }
        for (int r = 0; r < NRT; r++) {
            int rb = r * 128, ee = -1;
            for (int e = 0; e < NEXP; e++)
                if (rb >= offs[e] && rb < offs[e + 1]) ee = e;
            g_tile_e[r] = ee;
        }
    }
    for (int i = threadIdx.x; i < PMAX; i += blockDim.x) {
        g_pairid[i] = -1; g_pairwt[i] = 0.f;
    }
}

__global__ void k_scatter() {
    int t = blockIdx.x * blockDim.x + threadIdx.x;
    if (t >= T_TOK) return;
#pragma unroll
    for (int k = 0; k < 2; k++) {
        int e = g_sel[t * 2 + k];
        int pos = atomicAdd(&g_cursor[e], 1);
        g_pairid[pos] = t * 2 + k;
        g_pairwt[pos] = g_wt[t * 2 + k];
    }
}

// ---------------- prep: x -> packed bf16x2 hi/lo (k-pairs within a row) ----
__global__ __launch_bounds__(256) void k_prep_x(const float* __restrict__ x) {
    int g = blockIdx.x * blockDim.x + threadIdx.x;   // float4 index
    float4 v = *(const float4*)(x + (size_t)g * 4);
    uint32_t h01, l01, h23, l23;
    cvt_hilo(make_float2(v.x, v.y), h01, l01);
    cvt_hilo(make_float2(v.z, v.w), h23, l23);
    *(uint2*)(g_xp_h + (size_t)g * 2) = make_uint2(h01, h23);
    *(uint2*)(g_xp_l + (size_t)g * 2) = make_uint2(l01, l23);
}

// ---------------- up-proj: HMMA bf16x3, single-buffer smem, 2 CTAs/SM ------
__global__ __launch_bounds__(256, 2) void k_gemm_up(const float* __restrict__ w1) {
    const int r = blockIdx.y;
    const int e = g_tile_e[r];
    if (e < 0) return;
    const int cb = blockIdx.x;
    const int base = r * BM;

    __shared__ uint32_t Ah[BM][PADA], Al[BM][PADA];
    __shared__ uint32_t Bh[8][BROW], Bl[8][BROW];

    const int tid = threadIdx.x, lane = tid & 31, wid = tid >> 5;
    const int wm = wid & 3, wn = wid >> 2;
    const int gid = lane >> 2, tig = lane & 3;

    // A loader: 1 thread per (array, row); 2x uint4 = the row's 16-k chunk
    const int aarr = tid >> 7;               // 0 = hi, 1 = lo
    const int arow = tid & 127;
    const int pid = g_pairid[base + arow];
    const int rowsrc = (pid >= 0) ? (pid >> 1) : 0;
    const uint32_t* asrc = (aarr ? g_xp_l : g_xp_h) + (size_t)rowsrc * (DIM / 2);

    // B loader: kp = k-pair pair-of-rows, 4 consecutive n per thread (fp32 src)
    const int kp = tid >> 5;                 // 0..7
    const int n0 = (tid & 31) * 4;           // 0..124
    const float* bsrc = w1 + (size_t)(e * WEXP + cb * BN + n0);

    // register staging for chunk kt
    uint4 rA0 = *(const uint4*)(asrc);
    uint4 rA1 = *(const uint4*)(asrc + 4);
    float4 rB0 = *(const float4*)(bsrc + (size_t)(kp * 2) * EW);
    float4 rB1 = *(const float4*)(bsrc + (size_t)(kp * 2 + 1) * EW);

    float acc[2][8][4];
#pragma unroll
    for (int mi = 0; mi < 2; mi++)
#pragma unroll
        for (int ni = 0; ni < 8; ni++)
#pragma unroll
            for (int c = 0; c < 4; c++) acc[mi][ni][c] = 0.f;

    const int NKT = DIM / BK;
    for (int kt = 0; kt < NKT; kt++) {
        // ---- store phase (regs -> smem) ----
        {
            uint32_t (*Ad)[PADA] = aarr ? Al : Ah;
            *(uint4*)&Ad[arow][0] = rA0;
            *(uint4*)&Ad[arow][4] = rA1;
            uint32_t bh[4], bl[4];
            cvt_hilo(make_float2(rB0.x, rB1.x), bh[0], bl[0]);
            cvt_hilo(make_float2(rB0.y, rB1.y), bh[1], bl[1]);
            cvt_hilo(make_float2(rB0.z, rB1.z), bh[2], bl[2]);
            cvt_hilo(make_float2(rB0.w, rB1.w), bh[3], bl[3]);
            *(uint4*)&Bh[kp][n0] = make_uint4(bh[0], bh[1], bh[2], bh[3]);
            *(uint4*)&Bl[kp][n0] = make_uint4(bl[0], bl[1], bl[2], bl[3]);
        }
        __syncthreads();

        // ---- prefetch next chunk into regs (LDG overlaps compute below) ----
        if (kt + 1 < NKT) {
            rA0 = *(const uint4*)(asrc + (kt + 1) * 8);
            rA1 = *(const uint4*)(asrc + (kt + 1) * 8 + 4);
            const int k0 = (kt + 1) * 16 + kp * 2;
            rB0 = *(const float4*)(bsrc + (size_t)k0 * EW);
            rB1 = *(const float4*)(bsrc + (size_t)(k0 + 1) * EW);
        }

        // ---- compute phase ----
        uint32_t ah[2][4], al[2][4];
#pragma unroll
        for (int mi = 0; mi < 2; mi++) {
            const int row = wm * 32 + mi * 16 + gid;
            ah[mi][0] = Ah[row][tig];     al[mi][0] = Al[row][tig];
            ah[mi][1] = Ah[row + 8][tig]; al[mi][1] = Al[row + 8][tig];
            ah[mi][2] = Ah[row][tig + 4]; al[mi][2] = Al[row][tig + 4];
            ah[mi][3] = Ah[row + 8][tig + 4];
            al[mi][3] = Al[row + 8][tig + 4];
        }
#pragma unroll
        for (int t8 = 0; t8 < 8; t8++) {
            const int n = wn * 64 + t8 * 8 + gid;
            uint32_t bh0 = Bh[tig][n],     bh1 = Bh[tig + 4][n];
            uint32_t bl0 = Bl[tig][n],     bl1 = Bl[tig + 4][n];
#pragma unroll
            for (int mi = 0; mi < 2; mi++) {
                float* c = acc[mi][t8];
                MMA16816(c, ah[mi], bh0, bh1);
                MMA16816(c, al[mi], bh0, bh1);
                MMA16816(c, ah[mi], bl0, bl1);
            }
        }
        __syncthreads();
    }

    // epilogue: relu^2 -> packed hi/lo activation pairs
#pragma unroll
    for (int mi = 0; mi < 2; mi++) {
        const int row0 = base + wm * 32 + mi * 16 + gid;
        const int row1 = row0 + 8;
#pragma unroll
        for (int t8 = 0; t8 < 8; t8++) {
            const int col = cb * BN + wn * 64 + t8 * 8 + tig * 2;   // even
            float v0 = acc[mi][t8][0], v1 = acc[mi][t8][1];
            float v2 = acc[mi][t8][2], v3 = acc[mi][t8][3];
            v0 = fmaxf(v0, 0.f); v0 *= v0;
            v1 = fmaxf(v1, 0.f); v1 *= v1;
            v2 = fmaxf(v2, 0.f); v2 *= v2;
            v3 = fmaxf(v3, 0.f); v3 *= v3;
            uint32_t h01, l01, h23, l23;
            cvt_hilo(make_float2(v0, v1), h01, l01);
            cvt_hilo(make_float2(v2, v3), h23, l23);
            const size_t p0 = (size_t)row0 * (WEXP / 2) + (col >> 1);
            const size_t p1 = (size_t)row1 * (WEXP / 2) + (col >> 1);
            g_ap_h[p0] = h01; g_ap_l[p0] = l01;
            g_ap_h[p1] = h23; g_ap_l[p1] = l23;
        }
    }
}

// ---------------- down-proj: same engine, weighted scatter ----------------
__global__ __launch_bounds__(256, 2) void k_gemm_down(const float* __restrict__ w2) {
    const int r = blockIdx.y;
    const int e = g_tile_e[r];
    if (e < 0) return;
    const int cb = blockIdx.x;
    const int base = r * BM;

    __shared__ uint32_t Ah[BM][PADA], Al[BM][PADA];
    __shared__ uint32_t Bh[8][BROW], Bl[8][BROW];

    const int tid = threadIdx.x, lane = tid & 31, wid = tid >> 5;
    const int wm = wid & 3, wn = wid >> 2;
    const int gid = lane >> 2, tig = lane & 3;

    const int aarr = tid >> 7;
    const int arow = tid & 127;
    const uint32_t* asrc = (aarr ? g_ap_l : g_ap_h) + (size_t)(base + arow) * (WEXP / 2);

    const int kp = tid >> 5;
    const int n0 = (tid & 31) * 4;
    const float* bsrc = w2 + (size_t)e * WEXP * DIM + (size_t)(cb * BN + n0);

    uint4 rA0 = *(const uint4*)(asrc);
    uint4 rA1 = *(const uint4*)(asrc + 4);
    float4 rB0 = *(const float4*)(bsrc + (size_t)(kp * 2) * DIM);
    float4 rB1 = *(const float4*)(bsrc + (size_t)(kp * 2 + 1) * DIM);

    float acc[2][8][4];
#pragma unroll
    for (int mi = 0; mi < 2; mi++)
#pragma unroll
        for (int ni = 0; ni < 8; ni++)
#pragma unroll
            for (int c = 0; c < 4; c++) acc[mi][ni][c] = 0.f;

    const int NKT = WEXP / BK;
    for (int kt = 0; kt < NKT; kt++) {
        {
            uint32_t (*Ad)[PADA] = aarr ? Al : Ah;
            *(uint4*)&Ad[arow][0] = rA0;
            *(uint4*)&Ad[arow][4] = rA1;
            uint32_t bh[4], bl[4];
            cvt_hilo(make_float2(rB0.x, rB1.x), bh[0], bl[0]);
            cvt_hilo(make_float2(rB0.y, rB1.y), bh[1], bl[1]);
            cvt_hilo(make_float2(rB0.z, rB1.z), bh[2], bl[2]);
            cvt_hilo(make_float2(rB0.w, rB1.w), bh[3], bl[3]);
            *(uint4*)&Bh[kp][n0] = make_uint4(bh[0], bh[1], bh[2], bh[3]);
            *(uint4*)&Bl[kp][n0] = make_uint4(bl[0], bl[1], bl[2], bl[3]);
        }
        __syncthreads();

        if (kt + 1 < NKT) {
            rA0 = *(const uint4*)(asrc + (kt + 1) * 8);
            rA1 = *(const uint4*)(asrc + (kt + 1) * 8 + 4);
            const int k0 = (kt + 1) * 16 + kp * 2;
            rB0 = *(const float4*)(bsrc + (size_t)k0 * DIM);
            rB1 = *(const float4*)(bsrc + (size_t)(k0 + 1) * DIM);
        }

        uint32_t ah[2][4], al[2][4];
#pragma unroll
        for (int mi = 0; mi < 2; mi++) {
            const int row = wm * 32 + mi * 16 + gid;
            ah[mi][0] = Ah[row][tig];     al[mi][0] = Al[row][tig];
            ah[mi][1] = Ah[row + 8][tig]; al[mi][1] = Al[row + 8][tig];
            ah[mi][2] = Ah[row][tig + 4]; al[mi][2] = Al[row][tig + 4];
            ah[mi][3] = Ah[row + 8][tig + 4];
            al[mi][3] = Al[row + 8][tig + 4];
        }
#pragma unroll
        for (int t8 = 0; t8 < 8; t8++) {
            const int n = wn * 64 + t8 * 8 + gid;
            uint32_t bh0 = Bh[tig][n],     bh1 = Bh[tig + 4][n];
            uint32_t bl0 = Bl[tig][n],     bl1 = Bl[tig + 4][n];
#pragma unroll
            for (int mi = 0; mi < 2; mi++) {
                float* c = acc[mi][t8];
                MMA16816(c, ah[mi], bh0, bh1);
                MMA16816(c, al[mi], bh0, bh1);
                MMA16816(c, ah[mi], bl0, bl1);
            }
        }
        __syncthreads();
    }

    // epilogue: router-weight scale + deterministic per-slot scatter
#pragma unroll
    for (int mi = 0; mi < 2; mi++) {
        const int row0 = base + wm * 32 + mi * 16 + gid;
        const int row1 = row0 + 8;
        const int pid0 = g_pairid[row0], pid1 = g_pairid[row1];
        const float wt0 = g_pairwt[row0], wt1 = g_pairwt[row1];
        float* d0 = (pid0 >= 0)
            ? g_part + (size_t)(pid0 & 1) * ((size_t)T_TOK * DIM) + (size_t)(pid0 >> 1) * DIM
            : nullptr;
        float* d1 = (pid1 >= 0)
            ? g_part + (size_t)(pid1 & 1) * ((size_t)T_TOK * DIM) + (size_t)(pid1 >> 1) * DIM
            : nullptr;
#pragma unroll
        for (int t8 = 0; t8 < 8; t8++) {
            const int col = cb * BN + wn * 64 + t8 * 8 + tig * 2;
            if (d0) *(float2*)(d0 + col) =
                make_float2(wt0 * acc[mi][t8][0], wt0 * acc[mi][t8][1]);
            if (d1) *(float2*)(d1 + col) =
                make_float2(wt1 * acc[mi][t8][2], wt1 * acc[mi][t8][3]);
        }
    }
}

__global__ void k_combine(float* __restrict__ out) {
    const int i = blockIdx.x * blockDim.x + threadIdx.x;
    const float4* p0 = (const float4*)g_part;
    const float4* p1 = (const float4*)(g_part + (size_t)T_TOK * DIM);
    float4 a = p0[i], b = p1[i];
    ((float4*)out)[i] = make_float4(a.x + b.x, a.y + b.y, a.z + b.z, a.w + b.w);
}

extern "C" void kernel_launch(void* const* d_in, const int* in_sizes, int n_in,
                              void* d_out, int out_size) {
    const float* x  = (const float*)d_in[0];   // [4096, 1024]
    const float* rw = (const float*)d_in[1];   // [8, 1024]
    const float* w1 = (const float*)d_in[2];   // [1024, 8192]
    const float* w2 = (const float*)d_in[3];   // [8192, 1024]
    float* out = (float*)d_out;

    k_reset<<<1, 32>>>();
    k_router<<<T_TOK / 8, 256>>>(x, rw);
    k_setup<<<1, 256>>>();
    k_scatter<<<T_TOK / 256, 256>>>();
    k_prep_x<<<(T_TOK * DIM / 4) / 256, 256>>>(x);
    k_gemm_up<<<dim3(WEXP / BN, NRT), 256>>>(w1);
    k_gemm_down<<<dim3(DIM / BN, NRT), 256>>>(w2);
    k_combine<<<(T_TOK * DIM / 4) / 256, 256>>>(out);
}